// round 1
// baseline (speedup 1.0000x reference)
#include <cuda_runtime.h>

// Problem constants
#define SEQ   2048
#define BATCH 2
#define DIM   1024
#define NH    16
#define HD    64
#define MTOK  (SEQ * BATCH)   // 4096 tokens

// Scratch buffers (allocation-free rule: __device__ globals)
__device__ float g_q[MTOK * DIM];
__device__ float g_k[MTOK * DIM];
__device__ float g_v[MTOK * DIM];
__device__ float g_x[MTOK * DIM];

// ---------------------------------------------------------------------------
// GEMM: Y[M,N] = X[M,K] @ W[N,K]^T + bias[N]   (W stored torch-style [out,in])
// Block tile 128x128, K-tile 8, 256 threads, 8x8 accumulators per thread.
// ---------------------------------------------------------------------------
__global__ __launch_bounds__(256, 2)
void gemm_xt_kernel(const float* __restrict__ X, const float* __restrict__ W,
                    const float* __restrict__ bias, float* __restrict__ Y,
                    int M, int N, int K)
{
    __shared__ float Xs[8][132];   // k-major, padded (132 % 32 == 4 spreads banks)
    __shared__ float Ws[8][132];

    const int tid  = threadIdx.x;
    const int bm   = blockIdx.y;
    const int bn   = blockIdx.x;
    const int lrow = tid >> 1;          // 0..127
    const int lk   = (tid & 1) * 4;     // 0 or 4

    const float* Xp = X + (size_t)(bm * 128 + lrow) * K + lk;
    const float* Wp = W + (size_t)(bn * 128 + lrow) * K + lk;

    const int ty = tid >> 4;   // 0..15 (row group)
    const int tx = tid & 15;   // 0..15 (col group)

    float acc[8][8];
#pragma unroll
    for (int i = 0; i < 8; i++)
#pragma unroll
        for (int j = 0; j < 8; j++) acc[i][j] = 0.f;

    float4 xv = *(const float4*)Xp;
    float4 wv = *(const float4*)Wp;

    for (int k0 = 0; k0 < K; k0 += 8) {
        __syncthreads();
        Xs[lk + 0][lrow] = xv.x; Xs[lk + 1][lrow] = xv.y;
        Xs[lk + 2][lrow] = xv.z; Xs[lk + 3][lrow] = xv.w;
        Ws[lk + 0][lrow] = wv.x; Ws[lk + 1][lrow] = wv.y;
        Ws[lk + 2][lrow] = wv.z; Ws[lk + 3][lrow] = wv.w;
        __syncthreads();

        if (k0 + 8 < K) {   // prefetch next k-tile into registers
            xv = *(const float4*)(Xp + k0 + 8);
            wv = *(const float4*)(Wp + k0 + 8);
        }

#pragma unroll
        for (int kk = 0; kk < 8; kk++) {
            float4 a0 = *(const float4*)&Xs[kk][ty * 8];
            float4 a1 = *(const float4*)&Xs[kk][ty * 8 + 4];
            float4 b0 = *(const float4*)&Ws[kk][tx * 8];
            float4 b1 = *(const float4*)&Ws[kk][tx * 8 + 4];
            float a[8] = {a0.x, a0.y, a0.z, a0.w, a1.x, a1.y, a1.z, a1.w};
            float b[8] = {b0.x, b0.y, b0.z, b0.w, b1.x, b1.y, b1.z, b1.w};
#pragma unroll
            for (int i = 0; i < 8; i++)
#pragma unroll
                for (int j = 0; j < 8; j++)
                    acc[i][j] = fmaf(a[i], b[j], acc[i][j]);
        }
    }

    const int row0 = bm * 128 + ty * 8;
    const int col0 = bn * 128 + tx * 8;
#pragma unroll
    for (int i = 0; i < 8; i++) {
#pragma unroll
        for (int j = 0; j < 8; j += 4) {
            float4 r;
            r.x = acc[i][j + 0] + bias[col0 + j + 0];
            r.y = acc[i][j + 1] + bias[col0 + j + 1];
            r.z = acc[i][j + 2] + bias[col0 + j + 2];
            r.w = acc[i][j + 3] + bias[col0 + j + 3];
            *(float4*)&Y[(size_t)(row0 + i) * N + col0 + j] = r;
        }
    }
}

// ---------------------------------------------------------------------------
// Flash attention (unscaled QK^T, softmax over keys, then PV).
// One block handles 64 query rows of one (b,h); streams 64-key tiles.
// q/k/v layout: element (s,b,h,d) at s*2048 + b*1024 + h*64 + d.
// ---------------------------------------------------------------------------
#define BM 64
#define BN 64
#define ATTN_SMEM_FLOATS (4 * 64 * 68 + 3 * 64)

__global__ __launch_bounds__(256)
void attn_kernel(const float* __restrict__ q, const float* __restrict__ k,
                 const float* __restrict__ v, float* __restrict__ xout)
{
    extern __shared__ float sm[];
    float* Qs  = sm;              // [64 d][68] transposed: Qs[d*68 + r]
    float* Ks  = Qs + 64 * 68;    // [64 d][68] transposed: Ks[d*68 + c]
    float* Vs  = Ks + 64 * 68;    // [64 j][68] natural:    Vs[j*68 + d]
    float* Ss  = Vs + 64 * 68;    // [64 r][68] scores/probs
    float* m_s = Ss + 64 * 68;    // [64] running max
    float* l_s = m_s + 64;        // [64] running sum
    float* a_s = l_s + 64;        // [64] rescale factor

    const int tid = threadIdx.x;
    const int qt  = blockIdx.x;          // query tile
    const int bh  = blockIdx.y;          // b*H + h
    const int bb  = bh >> 4;
    const int hh  = bh & 15;
    const size_t head_off = (size_t)bb * DIM + (size_t)hh * HD;
    const size_t row_stride = (size_t)BATCH * DIM;   // 2048

    const int lr = tid >> 2;             // 0..63 (row to load)
    const int ld = (tid & 3) * 16;       // d-segment start

    // Load Q tile (transposed into smem)
    {
        const float* qp = q + (size_t)(qt * BM + lr) * row_stride + head_off + ld;
#pragma unroll
        for (int u = 0; u < 16; u += 4) {
            float4 t = *(const float4*)(qp + u);
            Qs[(ld + u + 0) * 68 + lr] = t.x;
            Qs[(ld + u + 1) * 68 + lr] = t.y;
            Qs[(ld + u + 2) * 68 + lr] = t.z;
            Qs[(ld + u + 3) * 68 + lr] = t.w;
        }
    }
    if (tid < 64) { m_s[tid] = -1e30f; l_s[tid] = 0.f; }

    const int ty = tid >> 4;   // 0..15 -> rows ty*4..+3
    const int tx = tid & 15;   // 0..15 -> cols tx*4..+3
    float o[4][4] = {};

    for (int kt = 0; kt < SEQ / BN; kt++) {
        __syncthreads();   // protects Qs init (iter 0) and prior-iter smem use
        // Load K (transposed) and V (natural) tiles
        {
            const float* kp = k + (size_t)(kt * BN + lr) * row_stride + head_off + ld;
            const float* vp = v + (size_t)(kt * BN + lr) * row_stride + head_off + ld;
#pragma unroll
            for (int u = 0; u < 16; u += 4) {
                float4 t = *(const float4*)(kp + u);
                Ks[(ld + u + 0) * 68 + lr] = t.x;
                Ks[(ld + u + 1) * 68 + lr] = t.y;
                Ks[(ld + u + 2) * 68 + lr] = t.z;
                Ks[(ld + u + 3) * 68 + lr] = t.w;
                float4 tv = *(const float4*)(vp + u);
                *(float4*)&Vs[lr * 68 + ld + u] = tv;
            }
        }
        __syncthreads();

        // S tile = Q @ K^T  (each thread 4x4)
        float s[4][4] = {};
#pragma unroll 8
        for (int dd = 0; dd < HD; dd++) {
            float4 a = *(const float4*)&Qs[dd * 68 + ty * 4];
            float4 b = *(const float4*)&Ks[dd * 68 + tx * 4];
            float av[4] = {a.x, a.y, a.z, a.w};
            float bv[4] = {b.x, b.y, b.z, b.w};
#pragma unroll
            for (int i = 0; i < 4; i++)
#pragma unroll
                for (int j = 0; j < 4; j++)
                    s[i][j] = fmaf(av[i], bv[j], s[i][j]);
        }
#pragma unroll
        for (int i = 0; i < 4; i++)
#pragma unroll
            for (int j = 0; j < 4; j++)
                Ss[(ty * 4 + i) * 68 + tx * 4 + j] = s[i][j];
        __syncthreads();

        // Online softmax update: one leader thread per row
        if (tid < 64) {
            float* row = Ss + tid * 68;
            float mx = -1e30f;
            for (int c = 0; c < BN; c++) mx = fmaxf(mx, row[c]);
            float mold  = m_s[tid];
            float mnew  = fmaxf(mold, mx);
            float alpha = __expf(mold - mnew);
            float sum = 0.f;
            for (int c = 0; c < BN; c++) {
                float p = __expf(row[c] - mnew);
                row[c] = p;
                sum += p;
            }
            l_s[tid] = l_s[tid] * alpha + sum;
            m_s[tid] = mnew;
            a_s[tid] = alpha;
        }
        __syncthreads();

        // Rescale O and accumulate P @ V
        float al[4];
#pragma unroll
        for (int i = 0; i < 4; i++) al[i] = a_s[ty * 4 + i];
#pragma unroll
        for (int i = 0; i < 4; i++)
#pragma unroll
            for (int j = 0; j < 4; j++) o[i][j] *= al[i];

        for (int j2 = 0; j2 < BN; j2++) {
            float4 vv = *(const float4*)&Vs[j2 * 68 + tx * 4];
            float vvv[4] = {vv.x, vv.y, vv.z, vv.w};
#pragma unroll
            for (int i = 0; i < 4; i++) {
                float p = Ss[(ty * 4 + i) * 68 + j2];
#pragma unroll
                for (int j = 0; j < 4; j++)
                    o[i][j] = fmaf(p, vvv[j], o[i][j]);
            }
        }
    }

    // Normalize and write out (same token layout as q/k/v)
    float linv[4];
#pragma unroll
    for (int i = 0; i < 4; i++) linv[i] = 1.f / l_s[ty * 4 + i];
#pragma unroll
    for (int i = 0; i < 4; i++) {
        float4 r;
        r.x = o[i][0] * linv[i];
        r.y = o[i][1] * linv[i];
        r.z = o[i][2] * linv[i];
        r.w = o[i][3] * linv[i];
        *(float4*)&xout[(size_t)(qt * BM + ty * 4 + i) * row_stride + head_off + tx * 4] = r;
    }
}

// ---------------------------------------------------------------------------
// kernel_launch: QKV projections -> flash attention -> output projection
// ---------------------------------------------------------------------------
extern "C" void kernel_launch(void* const* d_in, const int* in_sizes, int n_in,
                              void* d_out, int out_size)
{
    const float* query = (const float*)d_in[0];
    const float* key   = (const float*)d_in[1];
    const float* value = (const float*)d_in[2];
    const float* Wq    = (const float*)d_in[3];
    const float* bq    = (const float*)d_in[4];
    const float* Wk    = (const float*)d_in[5];
    const float* bk    = (const float*)d_in[6];
    const float* Wv    = (const float*)d_in[7];
    const float* bv    = (const float*)d_in[8];
    const float* Wo    = (const float*)d_in[9];
    const float* bo    = (const float*)d_in[10];
    float* out = (float*)d_out;

    float *qb, *kb, *vb, *xb;
    cudaGetSymbolAddress((void**)&qb, g_q);
    cudaGetSymbolAddress((void**)&kb, g_k);
    cudaGetSymbolAddress((void**)&vb, g_v);
    cudaGetSymbolAddress((void**)&xb, g_x);

    const int smem_bytes = ATTN_SMEM_FLOATS * (int)sizeof(float);   // 70400
    cudaFuncSetAttribute(attn_kernel,
                         cudaFuncAttributeMaxDynamicSharedMemorySize, smem_bytes);

    dim3 gemm_grid(DIM / 128, MTOK / 128);   // (8, 32)

    gemm_xt_kernel<<<gemm_grid, 256>>>(query, Wq, bq, qb, MTOK, DIM, DIM);
    gemm_xt_kernel<<<gemm_grid, 256>>>(key,   Wk, bk, kb, MTOK, DIM, DIM);
    gemm_xt_kernel<<<gemm_grid, 256>>>(value, Wv, bv, vb, MTOK, DIM, DIM);

    attn_kernel<<<dim3(SEQ / BM, BATCH * NH), 256, smem_bytes>>>(qb, kb, vb, xb);

    gemm_xt_kernel<<<gemm_grid, 256>>>(xb, Wo, bo, out, MTOK, DIM, DIM);
}

// round 3
// speedup vs baseline: 1.4809x; 1.4809x over previous
#include <cuda_runtime.h>
#include <cstdint>

// Problem constants
#define SEQ   2048
#define BATCH 2
#define DIM   1024
#define NH    16
#define HD    64
#define MTOK  (SEQ * BATCH)   // 4096 tokens

// Scratch buffers (allocation-free rule: __device__ globals)
__device__ float g_q[MTOK * DIM];
__device__ float g_k[MTOK * DIM];
__device__ float g_v[MTOK * DIM];
__device__ float g_x[MTOK * DIM];

// ===========================================================================
// Helpers (family-safe PTX only: cp.async + mma.sync, no tcgen05)
// ===========================================================================
__device__ __forceinline__ uint32_t sm_u32(const void* p) {
    return (uint32_t)__cvta_generic_to_shared(p);
}
__device__ __forceinline__ void cp_async16(uint32_t smem_addr, const void* gptr) {
    asm volatile("cp.async.cg.shared.global [%0], [%1], 16;" :: "r"(smem_addr), "l"(gptr) : "memory");
}
#define CP_COMMIT() asm volatile("cp.async.commit_group;" ::: "memory")
#define CP_WAIT1()  asm volatile("cp.async.wait_group 1;" ::: "memory")

__device__ __forceinline__ uint32_t f2tf32(float x) {
    uint32_t r;
    asm("cvt.rna.tf32.f32 %0, %1;" : "=r"(r) : "f"(x));
    return r;
}
// D += A@B, m16n8k8 tf32
__device__ __forceinline__ void mma_tf32(float* c, const uint32_t* a, const uint32_t* b) {
    asm volatile(
        "mma.sync.aligned.m16n8k8.row.col.f32.tf32.tf32.f32 "
        "{%0,%1,%2,%3}, {%4,%5,%6,%7}, {%8,%9}, {%0,%1,%2,%3};"
        : "+f"(c[0]), "+f"(c[1]), "+f"(c[2]), "+f"(c[3])
        : "r"(a[0]), "r"(a[1]), "r"(a[2]), "r"(a[3]), "r"(b[0]), "r"(b[1]));
}

// ===========================================================================
// tf32 tensor-core GEMM: Y[M,N] = X[M,K] @ W[N,K]^T + bias[N]
// CTA tile 128x128, 8 warps (each 64x32), K-chunk 32, 2-stage cp.async.
// SMEM: A[128][36] + B[128][36] per stage (pad 4 -> conflict-free frag loads).
// M=4096, N=K=1024 fixed.
// ===========================================================================
#define GSTAGES      2
#define SM_PITCH     36
#define AFLOATS      (128 * SM_PITCH)          // 4608 floats
#define STAGE_FLOATS (2 * AFLOATS)             // A + B
#define GEMM_DSMEM   (GSTAGES * STAGE_FLOATS * 4)   // 73728 bytes

__global__ __launch_bounds__(256, 2)
void gemm_mma_kernel(const float* __restrict__ X, const float* __restrict__ W,
                     const float* __restrict__ bias, float* __restrict__ Y)
{
    extern __shared__ float sm[];
    const int K = DIM, N = DIM;

    const int tid  = threadIdx.x;
    const int wid  = tid >> 5;
    const int lane = tid & 31;
    const int bm   = blockIdx.y;
    const int bn   = blockIdx.x;

    // loader mapping: each thread owns quad qd of rows r0, r0+32, r0+64, r0+96
    const int qd = tid & 7;
    const int r0 = tid >> 3;

    auto load_chunk = [&](int st, int c) {
        float* As = sm + st * STAGE_FLOATS;
        float* Bs = As + AFLOATS;
        const int k0 = c * 32;
        const float* xp = X + (size_t)(bm * 128 + r0) * K + k0 + qd * 4;
        const float* wp = W + (size_t)(bn * 128 + r0) * K + k0 + qd * 4;
#pragma unroll
        for (int i = 0; i < 4; i++) {
            const int r = r0 + 32 * i;
            cp_async16(sm_u32(&As[r * SM_PITCH + qd * 4]), xp + (size_t)(32 * i) * K);
            cp_async16(sm_u32(&Bs[r * SM_PITCH + qd * 4]), wp + (size_t)(32 * i) * K);
        }
        CP_COMMIT();
    };

    load_chunk(0, 0);
    load_chunk(1, 1);

    // warp tile: 64 rows x 32 cols
    const int wm = (wid & 1) * 64;
    const int wn = (wid >> 1) * 32;
    const int g  = lane >> 2;   // 0..7
    const int t  = lane & 3;    // 0..3

    float acc[4][4][4];
#pragma unroll
    for (int mt = 0; mt < 4; mt++)
#pragma unroll
        for (int nt = 0; nt < 4; nt++)
#pragma unroll
            for (int e = 0; e < 4; e++) acc[mt][nt][e] = 0.f;

    for (int c = 0; c < 32; c++) {
        const int st = c & 1;
        CP_WAIT1();
        __syncthreads();

        const float* As = sm + st * STAGE_FLOATS;
        const float* Bs = As + AFLOATS;

#pragma unroll
        for (int ks = 0; ks < 4; ks++) {
            const int k0 = ks * 8;
            uint32_t a[4][4], b[4][2];
#pragma unroll
            for (int mt = 0; mt < 4; mt++) {
                const float* ap = &As[(wm + mt * 16 + g) * SM_PITCH + k0 + t];
                a[mt][0] = f2tf32(ap[0]);
                a[mt][1] = f2tf32(ap[8 * SM_PITCH]);
                a[mt][2] = f2tf32(ap[4]);
                a[mt][3] = f2tf32(ap[8 * SM_PITCH + 4]);
            }
#pragma unroll
            for (int nt = 0; nt < 4; nt++) {
                const float* bp = &Bs[(wn + nt * 8 + g) * SM_PITCH + k0 + t];
                b[nt][0] = f2tf32(bp[0]);
                b[nt][1] = f2tf32(bp[4]);
            }
#pragma unroll
            for (int mt = 0; mt < 4; mt++)
#pragma unroll
                for (int nt = 0; nt < 4; nt++)
                    mma_tf32(acc[mt][nt], a[mt], b[nt]);
        }

        __syncthreads();
        const int cn = c + GSTAGES;
        if (cn < 32) load_chunk(st, cn);
        else         CP_COMMIT();          // keep wait_group accounting valid
    }

    // Epilogue: fragment c0,c1 -> (row, 2t / 2t+1); c2,c3 -> row+8
#pragma unroll
    for (int mt = 0; mt < 4; mt++) {
        const int row = bm * 128 + wm + mt * 16 + g;
#pragma unroll
        for (int nt = 0; nt < 4; nt++) {
            const int col = bn * 128 + wn + nt * 8 + 2 * t;
            float2 bi = *(const float2*)&bias[col];
            float2 r01, r23;
            r01.x = acc[mt][nt][0] + bi.x;
            r01.y = acc[mt][nt][1] + bi.y;
            r23.x = acc[mt][nt][2] + bi.x;
            r23.y = acc[mt][nt][3] + bi.y;
            *(float2*)&Y[(size_t)row * N + col]       = r01;
            *(float2*)&Y[(size_t)(row + 8) * N + col] = r23;
        }
    }
}

// ===========================================================================
// Flash attention (unscaled QK^T, softmax over keys, then PV). fp32.
// One block handles 64 query rows of one (b,h); streams 64-key tiles.
// q/k/v layout: element (s,b,h,d) at s*2048 + b*1024 + h*64 + d.
// ===========================================================================
#define BM 64
#define BN 64
#define ATTN_SMEM_FLOATS (4 * 64 * 68 + 3 * 64)

__global__ __launch_bounds__(256)
void attn_kernel(const float* __restrict__ q, const float* __restrict__ k,
                 const float* __restrict__ v, float* __restrict__ xout)
{
    extern __shared__ float sm[];
    float* Qs  = sm;              // [64 d][68] transposed: Qs[d*68 + r]
    float* Ks  = Qs + 64 * 68;    // [64 d][68] transposed: Ks[d*68 + c]
    float* Vs  = Ks + 64 * 68;    // [64 j][68] natural:    Vs[j*68 + d]
    float* Ss  = Vs + 64 * 68;    // [64 r][68] scores/probs
    float* m_s = Ss + 64 * 68;    // [64] running max
    float* l_s = m_s + 64;        // [64] running sum
    float* a_s = l_s + 64;        // [64] rescale factor

    const int tid = threadIdx.x;
    const int qt  = blockIdx.x;          // query tile
    const int bh  = blockIdx.y;          // b*H + h
    const int bb  = bh >> 4;
    const int hh  = bh & 15;
    const size_t head_off = (size_t)bb * DIM + (size_t)hh * HD;
    const size_t row_stride = (size_t)BATCH * DIM;   // 2048

    const int lr = tid >> 2;             // 0..63 (row to load)
    const int ld = (tid & 3) * 16;       // d-segment start

    // Load Q tile (transposed into smem)
    {
        const float* qp = q + (size_t)(qt * BM + lr) * row_stride + head_off + ld;
#pragma unroll
        for (int u = 0; u < 16; u += 4) {
            float4 t = *(const float4*)(qp + u);
            Qs[(ld + u + 0) * 68 + lr] = t.x;
            Qs[(ld + u + 1) * 68 + lr] = t.y;
            Qs[(ld + u + 2) * 68 + lr] = t.z;
            Qs[(ld + u + 3) * 68 + lr] = t.w;
        }
    }
    if (tid < 64) { m_s[tid] = -1e30f; l_s[tid] = 0.f; }

    const int ty = tid >> 4;   // 0..15 -> rows ty*4..+3
    const int tx = tid & 15;   // 0..15 -> cols tx*4..+3
    float o[4][4] = {};

    for (int kt = 0; kt < SEQ / BN; kt++) {
        __syncthreads();   // protects Qs init (iter 0) and prior-iter smem use
        // Load K (transposed) and V (natural) tiles
        {
            const float* kp = k + (size_t)(kt * BN + lr) * row_stride + head_off + ld;
            const float* vp = v + (size_t)(kt * BN + lr) * row_stride + head_off + ld;
#pragma unroll
            for (int u = 0; u < 16; u += 4) {
                float4 t = *(const float4*)(kp + u);
                Ks[(ld + u + 0) * 68 + lr] = t.x;
                Ks[(ld + u + 1) * 68 + lr] = t.y;
                Ks[(ld + u + 2) * 68 + lr] = t.z;
                Ks[(ld + u + 3) * 68 + lr] = t.w;
                float4 tv = *(const float4*)(vp + u);
                *(float4*)&Vs[lr * 68 + ld + u] = tv;
            }
        }
        __syncthreads();

        // S tile = Q @ K^T  (each thread 4x4)
        float s[4][4] = {};
#pragma unroll 8
        for (int dd = 0; dd < HD; dd++) {
            float4 a = *(const float4*)&Qs[dd * 68 + ty * 4];
            float4 b = *(const float4*)&Ks[dd * 68 + tx * 4];
            float av[4] = {a.x, a.y, a.z, a.w};
            float bv[4] = {b.x, b.y, b.z, b.w};
#pragma unroll
            for (int i = 0; i < 4; i++)
#pragma unroll
                for (int j = 0; j < 4; j++)
                    s[i][j] = fmaf(av[i], bv[j], s[i][j]);
        }
#pragma unroll
        for (int i = 0; i < 4; i++)
#pragma unroll
            for (int j = 0; j < 4; j++)
                Ss[(ty * 4 + i) * 68 + tx * 4 + j] = s[i][j];
        __syncthreads();

        // Online softmax: 4 threads per row (same warp), shfl reductions
        {
            const int r  = tid >> 2;
            const int c0 = (tid & 3) * 16;
            float* row = Ss + r * 68 + c0;
            float mx = -1e30f;
#pragma unroll
            for (int c = 0; c < 16; c += 4) {
                float4 t = *(const float4*)(row + c);
                mx = fmaxf(mx, fmaxf(fmaxf(t.x, t.y), fmaxf(t.z, t.w)));
            }
            mx = fmaxf(mx, __shfl_xor_sync(0xffffffffu, mx, 1));
            mx = fmaxf(mx, __shfl_xor_sync(0xffffffffu, mx, 2));
            float mold = m_s[r];
            float mnew = fmaxf(mold, mx);
            float sum = 0.f;
#pragma unroll
            for (int c = 0; c < 16; c += 4) {
                float4 t = *(const float4*)(row + c);
                t.x = __expf(t.x - mnew); t.y = __expf(t.y - mnew);
                t.z = __expf(t.z - mnew); t.w = __expf(t.w - mnew);
                *(float4*)(row + c) = t;
                sum += t.x + t.y + t.z + t.w;
            }
            sum += __shfl_xor_sync(0xffffffffu, sum, 1);
            sum += __shfl_xor_sync(0xffffffffu, sum, 2);   // full-warp sync: all m_s reads done
            if ((tid & 3) == 0) {
                float alpha = __expf(mold - mnew);
                l_s[r] = l_s[r] * alpha + sum;
                m_s[r] = mnew;
                a_s[r] = alpha;
            }
        }
        __syncthreads();

        // Rescale O and accumulate P @ V (vectorized Ss reads)
        float al[4];
#pragma unroll
        for (int i = 0; i < 4; i++) al[i] = a_s[ty * 4 + i];
#pragma unroll
        for (int i = 0; i < 4; i++)
#pragma unroll
            for (int j = 0; j < 4; j++) o[i][j] *= al[i];

        for (int j2 = 0; j2 < BN; j2 += 4) {
            float4 p0 = *(const float4*)&Ss[(ty * 4 + 0) * 68 + j2];
            float4 p1 = *(const float4*)&Ss[(ty * 4 + 1) * 68 + j2];
            float4 p2 = *(const float4*)&Ss[(ty * 4 + 2) * 68 + j2];
            float4 p3 = *(const float4*)&Ss[(ty * 4 + 3) * 68 + j2];
#pragma unroll
            for (int jj = 0; jj < 4; jj++) {
                float4 vv = *(const float4*)&Vs[(j2 + jj) * 68 + tx * 4];
                float pi0 = ((const float*)&p0)[jj];
                float pi1 = ((const float*)&p1)[jj];
                float pi2 = ((const float*)&p2)[jj];
                float pi3 = ((const float*)&p3)[jj];
                o[0][0] = fmaf(pi0, vv.x, o[0][0]); o[0][1] = fmaf(pi0, vv.y, o[0][1]);
                o[0][2] = fmaf(pi0, vv.z, o[0][2]); o[0][3] = fmaf(pi0, vv.w, o[0][3]);
                o[1][0] = fmaf(pi1, vv.x, o[1][0]); o[1][1] = fmaf(pi1, vv.y, o[1][1]);
                o[1][2] = fmaf(pi1, vv.z, o[1][2]); o[1][3] = fmaf(pi1, vv.w, o[1][3]);
                o[2][0] = fmaf(pi2, vv.x, o[2][0]); o[2][1] = fmaf(pi2, vv.y, o[2][1]);
                o[2][2] = fmaf(pi2, vv.z, o[2][2]); o[2][3] = fmaf(pi2, vv.w, o[2][3]);
                o[3][0] = fmaf(pi3, vv.x, o[3][0]); o[3][1] = fmaf(pi3, vv.y, o[3][1]);
                o[3][2] = fmaf(pi3, vv.z, o[3][2]); o[3][3] = fmaf(pi3, vv.w, o[3][3]);
            }
        }
    }

    // Normalize and write out (same token layout as q/k/v)
    float linv[4];
#pragma unroll
    for (int i = 0; i < 4; i++) linv[i] = 1.f / l_s[ty * 4 + i];
#pragma unroll
    for (int i = 0; i < 4; i++) {
        float4 r;
        r.x = o[i][0] * linv[i];
        r.y = o[i][1] * linv[i];
        r.z = o[i][2] * linv[i];
        r.w = o[i][3] * linv[i];
        *(float4*)&xout[(size_t)(qt * BM + ty * 4 + i) * row_stride + head_off + tx * 4] = r;
    }
}

// ---------------------------------------------------------------------------
// kernel_launch: QKV projections (tf32 mma.sync) -> flash attention -> O proj
// ---------------------------------------------------------------------------
extern "C" void kernel_launch(void* const* d_in, const int* in_sizes, int n_in,
                              void* d_out, int out_size)
{
    const float* query = (const float*)d_in[0];
    const float* key   = (const float*)d_in[1];
    const float* value = (const float*)d_in[2];
    const float* Wq    = (const float*)d_in[3];
    const float* bq    = (const float*)d_in[4];
    const float* Wk    = (const float*)d_in[5];
    const float* bk    = (const float*)d_in[6];
    const float* Wv    = (const float*)d_in[7];
    const float* bv    = (const float*)d_in[8];
    const float* Wo    = (const float*)d_in[9];
    const float* bo    = (const float*)d_in[10];
    float* out = (float*)d_out;

    float *qb, *kb, *vb, *xb;
    cudaGetSymbolAddress((void**)&qb, g_q);
    cudaGetSymbolAddress((void**)&kb, g_k);
    cudaGetSymbolAddress((void**)&vb, g_v);
    cudaGetSymbolAddress((void**)&xb, g_x);

    cudaFuncSetAttribute(gemm_mma_kernel,
                         cudaFuncAttributeMaxDynamicSharedMemorySize, GEMM_DSMEM);
    const int attn_smem = ATTN_SMEM_FLOATS * (int)sizeof(float);   // 70400
    cudaFuncSetAttribute(attn_kernel,
                         cudaFuncAttributeMaxDynamicSharedMemorySize, attn_smem);

    dim3 gemm_grid(DIM / 128, MTOK / 128);   // (8, 32)

    gemm_mma_kernel<<<gemm_grid, 256, GEMM_DSMEM>>>(query, Wq, bq, qb);
    gemm_mma_kernel<<<gemm_grid, 256, GEMM_DSMEM>>>(key,   Wk, bk, kb);
    gemm_mma_kernel<<<gemm_grid, 256, GEMM_DSMEM>>>(value, Wv, bv, vb);

    attn_kernel<<<dim3(SEQ / BM, BATCH * NH), 256, attn_smem>>>(qb, kb, vb, xb);

    gemm_mma_kernel<<<gemm_grid, 256, GEMM_DSMEM>>>(xb, Wo, bo, out);
}